// round 7
// baseline (speedup 1.0000x reference)
#include <cuda_runtime.h>
#include <cuda_fp16.h>
#include <math.h>
#include <cstdint>

#define S_LEN  2048
#define HIDDIM 4096
#define NH     32
#define NKV    8
#define HD     128
#define GROUPS 4
#define KVS    2048   // combined K|V row stride (fp32 elements)

// ---------------- scratch (allocation-free) ----------------
__device__ float g_Q [(size_t)S_LEN * HIDDIM];            // 32 MB
__device__ float g_KV[(size_t)S_LEN * KVS];               // 16 MB (K cols 0-1023 | V 1024-2047)
__device__ float g_O [(size_t)S_LEN * HIDDIM];            // 32 MB
// fp16 hi/lo planes
__device__ __half g_Hh [(size_t)S_LEN * HIDDIM],  g_Hl [(size_t)S_LEN * HIDDIM];
__device__ __half g_Wqh[(size_t)HIDDIM * HIDDIM], g_Wql[(size_t)HIDDIM * HIDDIM];
__device__ __half g_Wkvh[(size_t)KVS * HIDDIM],   g_Wkvl[(size_t)KVS * HIDDIM];
__device__ __half g_Woh[(size_t)HIDDIM * HIDDIM], g_Wol[(size_t)HIDDIM * HIDDIM];
__device__ __half g_Oh [(size_t)S_LEN * HIDDIM],  g_Ol [(size_t)S_LEN * HIDDIM];

// ---------------- common helpers ----------------
__device__ __forceinline__ uint32_t f2tf(float x) {
    uint32_t y;
    asm("cvt.rna.tf32.f32 %0, %1;" : "=r"(y) : "f"(x));
    return y;
}
__device__ __forceinline__ uint32_t smem_u32(const void* p) {
    uint32_t a;
    asm("{ .reg .u64 t; cvta.to.shared.u64 t, %1; cvt.u32.u64 %0, t; }" : "=r"(a) : "l"(p));
    return a;
}
__device__ __forceinline__ void mma16n8k8(float c[4], const uint32_t a[4],
                                          const uint32_t b[2]) {
    asm volatile(
        "mma.sync.aligned.m16n8k8.row.col.f32.tf32.tf32.f32 "
        "{%0,%1,%2,%3}, {%4,%5,%6,%7}, {%8,%9}, {%0,%1,%2,%3};"
        : "+f"(c[0]), "+f"(c[1]), "+f"(c[2]), "+f"(c[3])
        : "r"(a[0]), "r"(a[1]), "r"(a[2]), "r"(a[3]), "r"(b[0]), "r"(b[1]));
}
__device__ __forceinline__ void mma_f16(float c[4], const uint32_t a[4],
                                        const uint32_t b[2]) {
    asm volatile(
        "mma.sync.aligned.m16n8k16.row.col.f32.f16.f16.f32 "
        "{%0,%1,%2,%3}, {%4,%5,%6,%7}, {%8,%9}, {%0,%1,%2,%3};"
        : "+f"(c[0]), "+f"(c[1]), "+f"(c[2]), "+f"(c[3])
        : "r"(a[0]), "r"(a[1]), "r"(a[2]), "r"(a[3]), "r"(b[0]), "r"(b[1]));
}
__device__ __forceinline__ void ldm4(uint32_t r[4], uint32_t addr) {
    asm volatile("ldmatrix.sync.aligned.m8n8.x4.shared.b16 {%0,%1,%2,%3}, [%4];"
                 : "=r"(r[0]), "=r"(r[1]), "=r"(r[2]), "=r"(r[3]) : "r"(addr));
}
__device__ __forceinline__ void cp16(uint32_t dst, const void* src) {
    asm volatile("cp.async.cg.shared.global [%0], [%1], 16;" :: "r"(dst), "l"(src));
}

// ---------------- fp32 -> fp16 hi/lo split ----------------
__global__ void split_fp16(const float* __restrict__ X, __half* __restrict__ Xh,
                           __half* __restrict__ Xl, int n4) {
    int i = blockIdx.x * blockDim.x + threadIdx.x;
    if (i >= n4) return;
    float4 v = ((const float4*)X)[i];
    __half h0 = __float2half_rn(v.x), h1 = __float2half_rn(v.y);
    __half h2 = __float2half_rn(v.z), h3 = __float2half_rn(v.w);
    __half l0 = __float2half_rn(v.x - __half2float(h0));
    __half l1 = __float2half_rn(v.y - __half2float(h1));
    __half l2 = __float2half_rn(v.z - __half2float(h2));
    __half l3 = __float2half_rn(v.w - __half2float(h3));
    reinterpret_cast<__half2*>(Xh)[2 * i]     = __halves2half2(h0, h1);
    reinterpret_cast<__half2*>(Xh)[2 * i + 1] = __halves2half2(h2, h3);
    reinterpret_cast<__half2*>(Xl)[2 * i]     = __halves2half2(l0, l1);
    reinterpret_cast<__half2*>(Xl)[2 * i + 1] = __halves2half2(l2, l3);
}

// ================= split-fp16 GEMM: C = Ah@Bh^T + Ah@Bl^T + Al@Bh^T =================
// CTA tile 256x128, 512 threads (16 warps, 4x4 of 64x32), BK=16, 3 cp.async stages.
// 48-byte row pitch: ldmatrix banks (12r mod 32) all distinct -> conflict-free.

#define XBK    16
#define XPITCH 48
#define XAPL   (256 * XPITCH)            // 12288 B per A plane
#define XBPL   (128 * XPITCH)            // 6144 B per B plane
#define XSTG   (2 * XAPL + 2 * XBPL)     // 36864 B per stage
#define XNST   3
#define XSMEM  (XNST * XSTG)             // 110592 B

__global__ __launch_bounds__(512)
void gemm_fp16x3(const __half* __restrict__ Ah, const __half* __restrict__ Al,
                 const __half* __restrict__ Bh, const __half* __restrict__ Bl,
                 float* __restrict__ C, int M, int N, int K) {
    extern __shared__ char xsm[];
    const uint32_t sb = smem_u32(xsm);
    const int tid  = threadIdx.x;
    const int wid  = tid >> 5, lane = tid & 31;
    const int grp  = lane >> 2, thr4 = lane & 3;
    const int lrow = lane & 7,  quad = lane >> 3;
    const int warp_m = (wid & 3) * 64, warp_n = (wid >> 2) * 32;
    const int bm = blockIdx.y * 256, bn = blockIdx.x * 128;
    const int nk = K / XBK;

    // loader slots: 1536 16B-chunks/stage; 3 per thread (2 A, 1 B)
    const int cA0 = tid, cA1 = tid + 512;
    const int p0 = cA0 >> 9, r0_ = (cA0 >> 1) & 255, h0_ = cA0 & 1;
    const int p1 = cA1 >> 9, r1_ = (cA1 >> 1) & 255, h1_ = cA1 & 1;
    const int pb = tid >> 8, rb  = (tid >> 1) & 127, hb  = tid & 1;
    const __half* gA0 = (p0 ? Al : Ah) + (size_t)(bm + r0_) * K + h0_ * 8;
    const __half* gA1 = (p1 ? Al : Ah) + (size_t)(bm + r1_) * K + h1_ * 8;
    const __half* gB  = (pb ? Bl : Bh) + (size_t)(bn + rb) * K + hb * 8;
    const uint32_t sA0 = sb + p0 * XAPL + r0_ * XPITCH + h0_ * 16;
    const uint32_t sA1 = sb + p1 * XAPL + r1_ * XPITCH + h1_ * 16;
    const uint32_t sB  = sb + 2 * XAPL + pb * XBPL + rb * XPITCH + hb * 16;

    auto issue = [&](int kc) {
        uint32_t so = (uint32_t)((kc % XNST) * XSTG);
        size_t go = (size_t)kc * XBK;
        cp16(sA0 + so, gA0 + go);
        cp16(sA1 + so, gA1 + go);
        cp16(sB + so, gB + go);
    };

    // ldmatrix fragment addresses (hi planes; lo = +XAPL / +XBPL)
    uint32_t aoff[4], boff[2];
#pragma unroll
    for (int mt = 0; mt < 4; mt++)
        aoff[mt] = sb + (warp_m + mt * 16 + (quad & 1) * 8 + lrow) * XPITCH + (quad >> 1) * 16;
#pragma unroll
    for (int np = 0; np < 2; np++)
        boff[np] = sb + 2 * XAPL + (warp_n + np * 16 + (quad >> 1) * 8 + lrow) * XPITCH + (quad & 1) * 16;

    float acc[4][4][4];
#pragma unroll
    for (int mt = 0; mt < 4; mt++)
#pragma unroll
        for (int nt = 0; nt < 4; nt++)
#pragma unroll
            for (int i = 0; i < 4; i++) acc[mt][nt][i] = 0.f;

    issue(0);
    asm volatile("cp.async.commit_group;");
    issue(1);
    asm volatile("cp.async.commit_group;");

    for (int kc = 0; kc < nk; kc++) {
        asm volatile("cp.async.wait_group 1;" ::: "memory");
        __syncthreads();
        if (kc + 2 < nk) issue(kc + 2);
        asm volatile("cp.async.commit_group;");

        const uint32_t so = (uint32_t)((kc % XNST) * XSTG);

        uint32_t ah[4][4], bh[4][2], bl[4][2];
#pragma unroll
        for (int mt = 0; mt < 4; mt++) ldm4(ah[mt], aoff[mt] + so);
        {
            uint32_t t[4];
            ldm4(t, boff[0] + so);
            bh[0][0] = t[0]; bh[0][1] = t[1]; bh[1][0] = t[2]; bh[1][1] = t[3];
            ldm4(t, boff[1] + so);
            bh[2][0] = t[0]; bh[2][1] = t[1]; bh[3][0] = t[2]; bh[3][1] = t[3];
        }
#pragma unroll
        for (int mt = 0; mt < 4; mt++)
#pragma unroll
            for (int nt = 0; nt < 4; nt++)
                mma_f16(acc[mt][nt], ah[mt], bh[nt]);
        {
            uint32_t t[4];
            ldm4(t, boff[0] + XBPL + so);
            bl[0][0] = t[0]; bl[0][1] = t[1]; bl[1][0] = t[2]; bl[1][1] = t[3];
            ldm4(t, boff[1] + XBPL + so);
            bl[2][0] = t[0]; bl[2][1] = t[1]; bl[3][0] = t[2]; bl[3][1] = t[3];
        }
#pragma unroll
        for (int mt = 0; mt < 4; mt++)
#pragma unroll
            for (int nt = 0; nt < 4; nt++)
                mma_f16(acc[mt][nt], ah[mt], bl[nt]);
#pragma unroll
        for (int mt = 0; mt < 4; mt++) ldm4(ah[mt], aoff[mt] + XAPL + so);  // Al
#pragma unroll
        for (int mt = 0; mt < 4; mt++)
#pragma unroll
            for (int nt = 0; nt < 4; nt++)
                mma_f16(acc[mt][nt], ah[mt], bh[nt]);
    }

    // epilogue
#pragma unroll
    for (int mt = 0; mt < 4; mt++) {
        int row = bm + warp_m + mt * 16 + grp;
#pragma unroll
        for (int nt = 0; nt < 4; nt++) {
            int col = bn + warp_n + nt * 8 + thr4 * 2;
            *(float2*)(C + (size_t)row * N + col) =
                make_float2(acc[mt][nt][0], acc[mt][nt][1]);
            *(float2*)(C + (size_t)(row + 8) * N + col) =
                make_float2(acc[mt][nt][2], acc[mt][nt][3]);
        }
    }
}

// ---------------- RoPE (in-place on Q and combined KV) ----------------
__global__ void rope_kernel(float* __restrict__ Q, float* __restrict__ KV) {
    int idx = blockIdx.x * blockDim.x + threadIdx.x;
    const int total = S_LEN * (NH + NKV) * 64;
    if (idx >= total) return;
    int d   = idx & 63;
    int t   = idx >> 6;
    int h   = t % (NH + NKV);
    int pos = t / (NH + NKV);

    float invf = exp2f((float)d * -0.20762050593046014f);
    float ang  = (float)pos * invf;
    float sv, cv;
    sincosf(ang, &sv, &cv);

    float* base = (h < NH) ? (Q + (size_t)pos * HIDDIM + h * HD)
                           : (KV + (size_t)pos * KVS + (h - NH) * HD);
    float x1 = base[d];
    float x2 = base[d + 64];
    base[d]      = x1 * cv - x2 * sv;
    base[d + 64] = x2 * cv + x1 * sv;
}

// ---------------- Flash attention on tensor cores (tf32 mma.sync) ----------------
#define FA_LDK 132
#define FA_LDV 136
#define FA_SMEM ((64 * FA_LDK + 64 * FA_LDV) * (int)sizeof(float))

__global__ __launch_bounds__(128, 2)
void flash_attn_mma(const float* __restrict__ Q, const float* __restrict__ K,
                    const float* __restrict__ V, float* __restrict__ O) {
    extern __shared__ float smf[];
    float* Ks = smf;                       // [64][FA_LDK] tf32 bits
    float* Vs = smf + 64 * FA_LDK;         // [64][FA_LDV] tf32 bits

    const int qb   = blockIdx.x;
    const int h    = blockIdx.y;
    const int kv   = h / GROUPS;
    const int tid  = threadIdx.x;
    const int w    = tid >> 5;
    const int lane = tid & 31;
    const int grp  = lane >> 2;
    const int thr4 = lane & 3;

    const float scale = 0.08838834764831845f;  // 1/sqrt(128)

    uint32_t qf[16][4];
    const int r0 = qb * 64 + w * 16 + grp;
    const float* Qp0 = Q + (size_t)r0 * HIDDIM + h * HD;
    const float* Qp1 = Qp0 + (size_t)8 * HIDDIM;
#pragma unroll
    for (int kk = 0; kk < 16; kk++) {
        qf[kk][0] = f2tf(Qp0[kk * 8 + thr4] * scale);
        qf[kk][1] = f2tf(Qp1[kk * 8 + thr4] * scale);
        qf[kk][2] = f2tf(Qp0[kk * 8 + thr4 + 4] * scale);
        qf[kk][3] = f2tf(Qp1[kk * 8 + thr4 + 4] * scale);
    }

    float m0 = -1e30f, m1 = -1e30f, l0 = 0.f, l1 = 0.f;
    float o[16][4];
#pragma unroll
    for (int dt = 0; dt < 16; dt++)
#pragma unroll
        for (int i = 0; i < 4; i++) o[dt][i] = 0.f;

    const uint32_t* Ku = (const uint32_t*)Ks;
    const uint32_t* Vu = (const uint32_t*)Vs;

    for (int kt = 0; kt <= qb; kt++) {
        for (int e = tid; e < 64 * 32; e += 128) {
            int r = e >> 5, c4 = e & 31;
            size_t base = (size_t)(kt * 64 + r) * KVS + kv * HD + c4 * 4;
            float4 kq = *(const float4*)(K + base);
            float4 vq = *(const float4*)(V + base);
            *(uint4*)(Ks + r * FA_LDK + c4 * 4) =
                make_uint4(f2tf(kq.x), f2tf(kq.y), f2tf(kq.z), f2tf(kq.w));
            *(uint4*)(Vs + r * FA_LDV + c4 * 4) =
                make_uint4(f2tf(vq.x), f2tf(vq.y), f2tf(vq.z), f2tf(vq.w));
        }
        __syncthreads();

        float s[8][4];
#pragma unroll
        for (int nt = 0; nt < 8; nt++)
#pragma unroll
            for (int i = 0; i < 4; i++) s[nt][i] = 0.f;

#pragma unroll
        for (int kk = 0; kk < 16; kk++) {
#pragma unroll
            for (int nt = 0; nt < 8; nt++) {
                uint32_t b[2];
                b[0] = Ku[(nt * 8 + grp) * FA_LDK + kk * 8 + thr4];
                b[1] = Ku[(nt * 8 + grp) * FA_LDK + kk * 8 + thr4 + 4];
                mma16n8k8(s[nt], qf[kk], b);
            }
        }

        if (kt == qb) {
            int rl0 = w * 16 + grp, rl1 = rl0 + 8;
#pragma unroll
            for (int nt = 0; nt < 8; nt++) {
                int c = nt * 8 + thr4 * 2;
                if (c > rl0)     s[nt][0] = -1e30f;
                if (c + 1 > rl0) s[nt][1] = -1e30f;
                if (c > rl1)     s[nt][2] = -1e30f;
                if (c + 1 > rl1) s[nt][3] = -1e30f;
            }
        }

        float rm0 = -1e30f, rm1 = -1e30f;
#pragma unroll
        for (int nt = 0; nt < 8; nt++) {
            rm0 = fmaxf(rm0, fmaxf(s[nt][0], s[nt][1]));
            rm1 = fmaxf(rm1, fmaxf(s[nt][2], s[nt][3]));
        }
        rm0 = fmaxf(rm0, __shfl_xor_sync(0xffffffffu, rm0, 1));
        rm0 = fmaxf(rm0, __shfl_xor_sync(0xffffffffu, rm0, 2));
        rm1 = fmaxf(rm1, __shfl_xor_sync(0xffffffffu, rm1, 1));
        rm1 = fmaxf(rm1, __shfl_xor_sync(0xffffffffu, rm1, 2));
        float nm0 = fmaxf(m0, rm0), nm1 = fmaxf(m1, rm1);
        float a0 = __expf(m0 - nm0), a1 = __expf(m1 - nm1);
        float rs0 = 0.f, rs1 = 0.f;
#pragma unroll
        for (int nt = 0; nt < 8; nt++) {
            s[nt][0] = __expf(s[nt][0] - nm0);
            s[nt][1] = __expf(s[nt][1] - nm0);
            s[nt][2] = __expf(s[nt][2] - nm1);
            s[nt][3] = __expf(s[nt][3] - nm1);
            rs0 += s[nt][0] + s[nt][1];
            rs1 += s[nt][2] + s[nt][3];
        }
        rs0 += __shfl_xor_sync(0xffffffffu, rs0, 1);
        rs0 += __shfl_xor_sync(0xffffffffu, rs0, 2);
        rs1 += __shfl_xor_sync(0xffffffffu, rs1, 1);
        rs1 += __shfl_xor_sync(0xffffffffu, rs1, 2);
        l0 = l0 * a0 + rs0;
        l1 = l1 * a1 + rs1;
        m0 = nm0; m1 = nm1;
#pragma unroll
        for (int dt = 0; dt < 16; dt++) {
            o[dt][0] *= a0; o[dt][1] *= a0;
            o[dt][2] *= a1; o[dt][3] *= a1;
        }

        const int sl0 = (lane & 28) | (thr4 >> 1);
        const int sl1 = sl0 + 2;
        const bool odd = (thr4 & 1);
#pragma unroll
        for (int kk = 0; kk < 8; kk++) {
            float x0 = __shfl_sync(0xffffffffu, s[kk][0], sl0);
            float x1 = __shfl_sync(0xffffffffu, s[kk][1], sl0);
            float x2 = __shfl_sync(0xffffffffu, s[kk][2], sl0);
            float x3 = __shfl_sync(0xffffffffu, s[kk][3], sl0);
            float y0 = __shfl_sync(0xffffffffu, s[kk][0], sl1);
            float y1 = __shfl_sync(0xffffffffu, s[kk][1], sl1);
            float y2 = __shfl_sync(0xffffffffu, s[kk][2], sl1);
            float y3 = __shfl_sync(0xffffffffu, s[kk][3], sl1);
            uint32_t a[4];
            a[0] = f2tf(odd ? x1 : x0);
            a[1] = f2tf(odd ? x3 : x2);
            a[2] = f2tf(odd ? y1 : y0);
            a[3] = f2tf(odd ? y3 : y2);
#pragma unroll
            for (int dt = 0; dt < 16; dt++) {
                uint32_t b[2];
                b[0] = Vu[(kk * 8 + thr4) * FA_LDV + dt * 8 + grp];
                b[1] = Vu[(kk * 8 + thr4 + 4) * FA_LDV + dt * 8 + grp];
                mma16n8k8(o[dt], a, b);
            }
        }
        __syncthreads();
    }

    float inv0 = 1.f / l0, inv1 = 1.f / l1;
    float* Op0 = O + (size_t)r0 * HIDDIM + h * HD;
    float* Op1 = Op0 + (size_t)8 * HIDDIM;
#pragma unroll
    for (int dt = 0; dt < 16; dt++) {
        int c = dt * 8 + thr4 * 2;
        *(float2*)(Op0 + c) = make_float2(o[dt][0] * inv0, o[dt][1] * inv0);
        *(float2*)(Op1 + c) = make_float2(o[dt][2] * inv1, o[dt][3] * inv1);
    }
}

// ---------------- launch ----------------
extern "C" void kernel_launch(void* const* d_in, const int* in_sizes, int n_in,
                              void* d_out, int out_size) {
    const float* H  = (const float*)d_in[0];
    const float* Wq = (const float*)d_in[1];
    const float* Wk = (const float*)d_in[2];
    const float* Wv = (const float*)d_in[3];
    const float* Wo = (const float*)d_in[4];
    float* out = (float*)d_out;

    float *qb, *kvb, *ob;
    cudaGetSymbolAddress((void**)&qb, g_Q);
    cudaGetSymbolAddress((void**)&kvb, g_KV);
    cudaGetSymbolAddress((void**)&ob, g_O);
    __half *Hh, *Hl, *Wqh, *Wql, *Wkvh, *Wkvl, *Woh, *Wol, *Oh, *Ol;
    cudaGetSymbolAddress((void**)&Hh, g_Hh);   cudaGetSymbolAddress((void**)&Hl, g_Hl);
    cudaGetSymbolAddress((void**)&Wqh, g_Wqh); cudaGetSymbolAddress((void**)&Wql, g_Wql);
    cudaGetSymbolAddress((void**)&Wkvh, g_Wkvh); cudaGetSymbolAddress((void**)&Wkvl, g_Wkvl);
    cudaGetSymbolAddress((void**)&Woh, g_Woh); cudaGetSymbolAddress((void**)&Wol, g_Wol);
    cudaGetSymbolAddress((void**)&Oh, g_Oh);   cudaGetSymbolAddress((void**)&Ol, g_Ol);

    cudaFuncSetAttribute(gemm_fp16x3, cudaFuncAttributeMaxDynamicSharedMemorySize, XSMEM);
    cudaFuncSetAttribute(flash_attn_mma, cudaFuncAttributeMaxDynamicSharedMemorySize, FA_SMEM);

    const int TB = 256;
    // hi/lo splits
    split_fp16<<<(S_LEN * HIDDIM / 4 + TB - 1) / TB, TB>>>(H, Hh, Hl, S_LEN * HIDDIM / 4);
    split_fp16<<<(HIDDIM * HIDDIM / 4 + TB - 1) / TB, TB>>>(Wq, Wqh, Wql, HIDDIM * HIDDIM / 4);
    split_fp16<<<(NKV * HD * HIDDIM / 4 + TB - 1) / TB, TB>>>(Wk, Wkvh, Wkvl, NKV * HD * HIDDIM / 4);
    split_fp16<<<(NKV * HD * HIDDIM / 4 + TB - 1) / TB, TB>>>(
        Wv, Wkvh + (size_t)NKV * HD * HIDDIM, Wkvl + (size_t)NKV * HD * HIDDIM,
        NKV * HD * HIDDIM / 4);
    split_fp16<<<(HIDDIM * HIDDIM / 4 + TB - 1) / TB, TB>>>(Wo, Woh, Wol, HIDDIM * HIDDIM / 4);

    // projections: Q, fused K|V
    gemm_fp16x3<<<dim3(HIDDIM / 128, S_LEN / 256), 512, XSMEM>>>(Hh, Hl, Wqh, Wql, qb,
                                                                 S_LEN, HIDDIM, HIDDIM);
    gemm_fp16x3<<<dim3(KVS / 128, S_LEN / 256), 512, XSMEM>>>(Hh, Hl, Wkvh, Wkvl, kvb,
                                                              S_LEN, KVS, HIDDIM);
    // RoPE
    rope_kernel<<<(S_LEN * (NH + NKV) * 64) / 256, 256>>>(qb, kvb);

    // attention (tensor cores), V = KV cols 1024..2047
    flash_attn_mma<<<dim3(S_LEN / 64, NH), 128, FA_SMEM>>>(qb, kvb, kvb + NKV * HD, ob);

    // output projection
    split_fp16<<<(S_LEN * HIDDIM / 4 + TB - 1) / TB, TB>>>(ob, Oh, Ol, S_LEN * HIDDIM / 4);
    gemm_fp16x3<<<dim3(HIDDIM / 128, S_LEN / 256), 512, XSMEM>>>(Oh, Ol, Woh, Wol, out,
                                                                 S_LEN, HIDDIM, HIDDIM);
}

// round 12
// speedup vs baseline: 2.5953x; 2.5953x over previous
#include <cuda_runtime.h>
#include <cuda_fp16.h>
#include <math.h>
#include <cstdint>

#define S_LEN  2048
#define HIDDIM 4096
#define NH     32
#define NKV    8
#define HD     128
#define GROUPS 4
#define QKVN   6144   // fused projection width: Q 0-4095 | K 4096-5119 | V 5120-6143
#define KVS    2048   // fp16 KV row: K halves 0-1023 | V 1024-2047

// ---------------- scratch (allocation-free) ----------------
__device__ float  g_QKV[(size_t)S_LEN * QKVN];            // fp32 fused projections
__device__ __half g_Hh [(size_t)S_LEN * HIDDIM];
__device__ __half g_Wqkvh[(size_t)QKVN * HIDDIM];
__device__ __half g_Woh[(size_t)HIDDIM * HIDDIM];
__device__ __half g_Qh [(size_t)S_LEN * HIDDIM];          // roped+scaled fp16 Q
__device__ __half g_KVh[(size_t)S_LEN * KVS];             // roped fp16 K | fp16 V
__device__ __half g_Oh [(size_t)S_LEN * HIDDIM];          // attention out fp16

// ---------------- helpers ----------------
__device__ __forceinline__ uint32_t smem_u32(const void* p) {
    uint32_t a;
    asm("{ .reg .u64 t; cvta.to.shared.u64 t, %1; cvt.u32.u64 %0, t; }" : "=r"(a) : "l"(p));
    return a;
}
__device__ __forceinline__ void mma_f16(float c[4], const uint32_t a[4],
                                        const uint32_t b[2]) {
    asm volatile(
        "mma.sync.aligned.m16n8k16.row.col.f32.f16.f16.f32 "
        "{%0,%1,%2,%3}, {%4,%5,%6,%7}, {%8,%9}, {%0,%1,%2,%3};"
        : "+f"(c[0]), "+f"(c[1]), "+f"(c[2]), "+f"(c[3])
        : "r"(a[0]), "r"(a[1]), "r"(a[2]), "r"(a[3]), "r"(b[0]), "r"(b[1]));
}
__device__ __forceinline__ void ldm4(uint32_t r[4], uint32_t addr) {
    asm volatile("ldmatrix.sync.aligned.m8n8.x4.shared.b16 {%0,%1,%2,%3}, [%4];"
                 : "=r"(r[0]), "=r"(r[1]), "=r"(r[2]), "=r"(r[3]) : "r"(addr));
}
__device__ __forceinline__ void ldm4t(uint32_t r[4], uint32_t addr) {
    asm volatile("ldmatrix.sync.aligned.m8n8.x4.trans.shared.b16 {%0,%1,%2,%3}, [%4];"
                 : "=r"(r[0]), "=r"(r[1]), "=r"(r[2]), "=r"(r[3]) : "r"(addr));
}
__device__ __forceinline__ void cp16(uint32_t dst, const void* src) {
    asm volatile("cp.async.cg.shared.global [%0], [%1], 16;" :: "r"(dst), "l"(src));
}
__device__ __forceinline__ uint32_t packh2(float lo, float hi) {
    __half2 h = __floats2half2_rn(lo, hi);
    return *reinterpret_cast<uint32_t*>(&h);
}

// ---------------- fp32 -> fp16 convert ----------------
__global__ void cvt_fp16(const float* __restrict__ X, __half* __restrict__ Xh, int n4) {
    int i = blockIdx.x * blockDim.x + threadIdx.x;
    if (i >= n4) return;
    float4 v = ((const float4*)X)[i];
    __half2 a = __floats2half2_rn(v.x, v.y);
    __half2 b = __floats2half2_rn(v.z, v.w);
    reinterpret_cast<__half2*>(Xh)[2 * i]     = a;
    reinterpret_cast<__half2*>(Xh)[2 * i + 1] = b;
}

// ================= single-pass fp16 GEMM: C = A @ B^T =================
// CTA 256x128, 512 threads (16 warps, 4x4 of 64x32), BK=32, 3 cp.async stages.
// 80-byte row pitch: ldmatrix banks (20r mod 32) distinct over 8 rows.

#define XBK    32
#define XPITCH 80
#define XAPL   (256 * XPITCH)            // 20480 B
#define XBPL   (128 * XPITCH)            // 10240 B
#define XSTG   (XAPL + XBPL)             // 30720 B
#define XNST   3
#define XSMEM  (XNST * XSTG)             // 92160 B

__global__ __launch_bounds__(512)
void gemm_fp16(const __half* __restrict__ A, const __half* __restrict__ B,
               float* __restrict__ C, int M, int N, int K) {
    extern __shared__ char xsm[];
    const uint32_t sb = smem_u32(xsm);
    const int tid  = threadIdx.x;
    const int wid  = tid >> 5, lane = tid & 31;
    const int grp  = lane >> 2, thr4 = lane & 3;
    const int lrow = lane & 7,  quad = lane >> 3;
    const int warp_m = (wid & 3) * 64, warp_n = (wid >> 2) * 32;
    const int bm = blockIdx.y * 256, bn = blockIdx.x * 128;
    const int nk = K / XBK;

    // loader: A 1024 chunks (256 rows x 4), B 512 chunks; 3 per thread
    const int r0 = tid >> 2,        h0 = tid & 3;           // A rows 0-127
    const int r1 = (tid >> 2) + 128, h1 = h0;               // A rows 128-255
    const int rb = tid >> 2,        hb = tid & 3;           // B rows 0-127
    const __half* gA0 = A + (size_t)(bm + r0) * K + h0 * 8;
    const __half* gA1 = A + (size_t)(bm + r1) * K + h1 * 8;
    const __half* gB  = B + (size_t)(bn + rb) * K + hb * 8;
    const uint32_t sA0 = sb + r0 * XPITCH + h0 * 16;
    const uint32_t sA1 = sb + r1 * XPITCH + h1 * 16;
    const uint32_t sB  = sb + XAPL + rb * XPITCH + hb * 16;

    auto issue = [&](int kc) {
        uint32_t so = (uint32_t)((kc % XNST) * XSTG);
        size_t go = (size_t)kc * XBK;
        cp16(sA0 + so, gA0 + go);
        cp16(sA1 + so, gA1 + go);
        cp16(sB + so, gB + go);
    };

    // ldmatrix bases
    uint32_t aoff[4], boff[2];
#pragma unroll
    for (int mt = 0; mt < 4; mt++)
        aoff[mt] = sb + (warp_m + mt * 16 + (quad & 1) * 8 + lrow) * XPITCH + (quad >> 1) * 16;
#pragma unroll
    for (int np = 0; np < 2; np++)
        boff[np] = sb + XAPL + (warp_n + np * 16 + (quad >> 1) * 8 + lrow) * XPITCH + (quad & 1) * 16;

    float acc[4][4][4];
#pragma unroll
    for (int mt = 0; mt < 4; mt++)
#pragma unroll
        for (int nt = 0; nt < 4; nt++)
#pragma unroll
            for (int i = 0; i < 4; i++) acc[mt][nt][i] = 0.f;

    issue(0);
    asm volatile("cp.async.commit_group;");
    issue(1);
    asm volatile("cp.async.commit_group;");

    for (int kc = 0; kc < nk; kc++) {
        asm volatile("cp.async.wait_group 1;" ::: "memory");
        __syncthreads();
        if (kc + 2 < nk) issue(kc + 2);
        asm volatile("cp.async.commit_group;");

        const uint32_t so = (uint32_t)((kc % XNST) * XSTG);
#pragma unroll
        for (int k16 = 0; k16 < 2; k16++) {
            const uint32_t ko = so + k16 * 32;
            uint32_t ah[4][4], bf[4][2];
#pragma unroll
            for (int mt = 0; mt < 4; mt++) ldm4(ah[mt], aoff[mt] + ko);
            {
                uint32_t t[4];
                ldm4(t, boff[0] + ko);
                bf[0][0] = t[0]; bf[0][1] = t[1]; bf[1][0] = t[2]; bf[1][1] = t[3];
                ldm4(t, boff[1] + ko);
                bf[2][0] = t[0]; bf[2][1] = t[1]; bf[3][0] = t[2]; bf[3][1] = t[3];
            }
#pragma unroll
            for (int mt = 0; mt < 4; mt++)
#pragma unroll
                for (int nt = 0; nt < 4; nt++)
                    mma_f16(acc[mt][nt], ah[mt], bf[nt]);
        }
    }

#pragma unroll
    for (int mt = 0; mt < 4; mt++) {
        int row = bm + warp_m + mt * 16 + grp;
#pragma unroll
        for (int nt = 0; nt < 4; nt++) {
            int col = bn + warp_n + nt * 8 + thr4 * 2;
            *(float2*)(C + (size_t)row * N + col) =
                make_float2(acc[mt][nt][0], acc[mt][nt][1]);
            *(float2*)(C + (size_t)(row + 8) * N + col) =
                make_float2(acc[mt][nt][2], acc[mt][nt][3]);
        }
    }
}

// ---------------- RoPE + fp16 convert ----------------
// units: 0-31 Q heads (rope, * 1/sqrt(128)), 32-39 K heads (rope), 40-47 V heads (cvt)
__global__ void rope_cvt(const float* __restrict__ QKV, __half* __restrict__ Qh,
                         __half* __restrict__ KVh) {
    int idx = blockIdx.x * blockDim.x + threadIdx.x;
    const int total = S_LEN * 48 * 64;
    if (idx >= total) return;
    int d   = idx & 63;
    int t   = idx >> 6;
    int u   = t % 48;
    int pos = t / 48;
    const float scale = 0.08838834764831845f;

    if (u < 40) {
        float invf = exp2f((float)d * -0.20762050593046014f);
        float ang  = (float)pos * invf;
        float sv, cv;
        sincosf(ang, &sv, &cv);
        if (u < NH) {
            const float* in = QKV + (size_t)pos * QKVN + u * HD;
            __half* out = Qh + (size_t)pos * HIDDIM + u * HD;
            float x1 = in[d], x2 = in[d + 64];
            out[d]      = __float2half_rn((x1 * cv - x2 * sv) * scale);
            out[d + 64] = __float2half_rn((x2 * cv + x1 * sv) * scale);
        } else {
            int kh = u - NH;
            const float* in = QKV + (size_t)pos * QKVN + HIDDIM + kh * HD;
            __half* out = KVh + (size_t)pos * KVS + kh * HD;
            float x1 = in[d], x2 = in[d + 64];
            out[d]      = __float2half_rn(x1 * cv - x2 * sv);
            out[d + 64] = __float2half_rn(x2 * cv + x1 * sv);
        }
    } else {
        int vh = u - 40;
        const float* in = QKV + (size_t)pos * QKVN + HIDDIM + NKV * HD + vh * HD;
        __half* out = KVh + (size_t)pos * KVS + NKV * HD + vh * HD;
        out[d]      = __float2half_rn(in[d]);
        out[d + 64] = __float2half_rn(in[d + 64]);
    }
}

// ---------------- fp16 flash attention ----------------
// CTA = (64 q rows, head), 4 warps. K/V tiles 64x128 halves, pitch 272B,
// double-buffered cp.async. Zero-shuffle P relayout (C-frag == A-frag packing).

#define KP      272                       // bytes per K/V smem row
#define FA_TILE (64 * KP)                 // 17408 B
#define FA_BUF  (2 * FA_TILE)             // K+V
#define FA_SMEM (2 * FA_BUF)              // 69632 B

__global__ __launch_bounds__(128, 2)
void flash_attn_fp16(const __half* __restrict__ Qh, const __half* __restrict__ KVh,
                     __half* __restrict__ Oh) {
    extern __shared__ char fsm[];
    const uint32_t sb = smem_u32(fsm);

    const int qb   = blockIdx.x;
    const int h    = blockIdx.y;
    const int kv   = h / GROUPS;
    const int tid  = threadIdx.x;
    const int w    = tid >> 5;
    const int lane = tid & 31;
    const int grp  = lane >> 2;
    const int thr4 = lane & 3;
    const int lrow = lane & 7, quad = lane >> 3;

    // staging: 2048 chunks per kt (K tile 1024 + V tile 1024), 16 per thread
    auto stage = [&](int kt, int buf) {
        uint32_t dbase = sb + buf * FA_BUF;
#pragma unroll
        for (int i = 0; i < 16; i++) {
            int c = i * 128 + tid;
            int tile = c >> 10, r = (c >> 4) & 63, hx = c & 15;
            const __half* src = KVh + (size_t)(kt * 64 + r) * KVS + tile * (NKV * HD)
                              + kv * HD + hx * 8;
            cp16(dbase + tile * FA_TILE + r * KP + hx * 16, src);
        }
    };

    // Q fragments (8 k16 steps over d=128)
    uint32_t qf[8][4];
    const int r0 = qb * 64 + w * 16 + grp;
    const __half* Qp0 = Qh + (size_t)r0 * HIDDIM + h * HD;
    const __half* Qp1 = Qp0 + (size_t)8 * HIDDIM;
#pragma unroll
    for (int kk = 0; kk < 8; kk++) {
        qf[kk][0] = *(const uint32_t*)(Qp0 + 16 * kk + 2 * thr4);
        qf[kk][1] = *(const uint32_t*)(Qp1 + 16 * kk + 2 * thr4);
        qf[kk][2] = *(const uint32_t*)(Qp0 + 16 * kk + 8 + 2 * thr4);
        qf[kk][3] = *(const uint32_t*)(Qp1 + 16 * kk + 8 + 2 * thr4);
    }

    float m0 = -1e30f, m1 = -1e30f, l0 = 0.f, l1 = 0.f;
    float o[16][4];
#pragma unroll
    for (int dt = 0; dt < 16; dt++)
#pragma unroll
        for (int i = 0; i < 4; i++) o[dt][i] = 0.f;

    // ldmatrix lane bases
    const uint32_t kb_row = (quad >> 1) * 8 + lrow;        // K: rows n, col block (quad&1)
    const uint32_t kb_col = (quad & 1) * 16;
    const uint32_t vb_row = (quad & 1) * 8 + lrow;         // V trans: rows k, col (quad>>1)
    const uint32_t vb_col = (quad >> 1) * 16;

    stage(0, 0);
    asm volatile("cp.async.commit_group;");

    for (int kt = 0; kt <= qb; kt++) {
        if (kt < qb) stage(kt + 1, (kt + 1) & 1);
        asm volatile("cp.async.commit_group;");
        asm volatile("cp.async.wait_group 1;" ::: "memory");
        __syncthreads();

        const uint32_t Ksb = sb + (kt & 1) * FA_BUF;
        const uint32_t Vsb = Ksb + FA_TILE;

        // ---- S = Qs @ K^T ----
        float s[8][4];
#pragma unroll
        for (int nt = 0; nt < 8; nt++)
#pragma unroll
            for (int i = 0; i < 4; i++) s[nt][i] = 0.f;

#pragma unroll
        for (int kk = 0; kk < 8; kk++) {
            uint32_t bf[8][2];
#pragma unroll
            for (int nn = 0; nn < 4; nn++) {
                uint32_t t[4];
                ldm4(t, Ksb + (nn * 16 + kb_row) * KP + kk * 32 + kb_col);
                bf[2 * nn][0] = t[0]; bf[2 * nn][1] = t[1];
                bf[2 * nn + 1][0] = t[2]; bf[2 * nn + 1][1] = t[3];
            }
#pragma unroll
            for (int nt = 0; nt < 8; nt++)
                mma_f16(s[nt], qf[kk], bf[nt]);
        }

        if (kt == qb) {  // causal mask on diagonal tile
            int rl0 = w * 16 + grp, rl1 = rl0 + 8;
#pragma unroll
            for (int nt = 0; nt < 8; nt++) {
                int c = nt * 8 + thr4 * 2;
                if (c > rl0)     s[nt][0] = -1e30f;
                if (c + 1 > rl0) s[nt][1] = -1e30f;
                if (c > rl1)     s[nt][2] = -1e30f;
                if (c + 1 > rl1) s[nt][3] = -1e30f;
            }
        }

        // ---- online softmax ----
        float rm0 = -1e30f, rm1 = -1e30f;
#pragma unroll
        for (int nt = 0; nt < 8; nt++) {
            rm0 = fmaxf(rm0, fmaxf(s[nt][0], s[nt][1]));
            rm1 = fmaxf(rm1, fmaxf(s[nt][2], s[nt][3]));
        }
        rm0 = fmaxf(rm0, __shfl_xor_sync(0xffffffffu, rm0, 1));
        rm0 = fmaxf(rm0, __shfl_xor_sync(0xffffffffu, rm0, 2));
        rm1 = fmaxf(rm1, __shfl_xor_sync(0xffffffffu, rm1, 1));
        rm1 = fmaxf(rm1, __shfl_xor_sync(0xffffffffu, rm1, 2));
        float nm0 = fmaxf(m0, rm0), nm1 = fmaxf(m1, rm1);
        float a0 = __expf(m0 - nm0), a1 = __expf(m1 - nm1);
        float rs0 = 0.f, rs1 = 0.f;
#pragma unroll
        for (int nt = 0; nt < 8; nt++) {
            s[nt][0] = __expf(s[nt][0] - nm0);
            s[nt][1] = __expf(s[nt][1] - nm0);
            s[nt][2] = __expf(s[nt][2] - nm1);
            s[nt][3] = __expf(s[nt][3] - nm1);
            rs0 += s[nt][0] + s[nt][1];
            rs1 += s[nt][2] + s[nt][3];
        }
        rs0 += __shfl_xor_sync(0xffffffffu, rs0, 1);
        rs0 += __shfl_xor_sync(0xffffffffu, rs0, 2);
        rs1 += __shfl_xor_sync(0xffffffffu, rs1, 1);
        rs1 += __shfl_xor_sync(0xffffffffu, rs1, 2);
        l0 = l0 * a0 + rs0;
        l1 = l1 * a1 + rs1;
        m0 = nm0; m1 = nm1;
#pragma unroll
        for (int dt = 0; dt < 16; dt++) {
            o[dt][0] *= a0; o[dt][1] *= a0;
            o[dt][2] *= a1; o[dt][3] *= a1;
        }

        // ---- O += P @ V  (P packs directly into A fragments) ----
        // dd covers ALL 8 d-blocks of 16 (fix for the half-missing-output bug)
#pragma unroll
        for (int kk2 = 0; kk2 < 4; kk2++) {
            uint32_t a[4];
            a[0] = packh2(s[2 * kk2][0],     s[2 * kk2][1]);
            a[1] = packh2(s[2 * kk2][2],     s[2 * kk2][3]);
            a[2] = packh2(s[2 * kk2 + 1][0], s[2 * kk2 + 1][1]);
            a[3] = packh2(s[2 * kk2 + 1][2], s[2 * kk2 + 1][3]);
#pragma unroll
            for (int dd = 0; dd < 8; dd++) {
                uint32_t t[4];
                ldm4t(t, Vsb + (kk2 * 16 + vb_row) * KP + dd * 32 + vb_col);
                uint32_t b0[2] = {t[0], t[1]};
                uint32_t b1[2] = {t[2], t[3]};
                mma_f16(o[2 * dd],     a, b0);
                mma_f16(o[2 * dd + 1], a, b1);
            }
        }
        __syncthreads();
    }

    // epilogue: normalize, write fp16
    float inv0 = 1.f / l0, inv1 = 1.f / l1;
    __half* Op0 = Oh + (size_t)r0 * HIDDIM + h * HD;
    __half* Op1 = Op0 + (size_t)8 * HIDDIM;
#pragma unroll
    for (int dt = 0; dt < 16; dt++) {
        int c = dt * 8 + thr4 * 2;
        *(uint32_t*)(Op0 + c) = packh2(o[dt][0] * inv0, o[dt][1] * inv0);
        *(uint32_t*)(Op1 + c) = packh2(o[dt][2] * inv1, o[dt][3] * inv1);
    }
}

// ---------------- launch ----------------
extern "C" void kernel_launch(void* const* d_in, const int* in_sizes, int n_in,
                              void* d_out, int out_size) {
    const float* H  = (const float*)d_in[0];
    const float* Wq = (const float*)d_in[1];
    const float* Wk = (const float*)d_in[2];
    const float* Wv = (const float*)d_in[3];
    const float* Wo = (const float*)d_in[4];
    float* out = (float*)d_out;

    float* qkv;
    cudaGetSymbolAddress((void**)&qkv, g_QKV);
    __half *Hh, *Wqkvh, *Woh, *Qh, *KVh, *Oh;
    cudaGetSymbolAddress((void**)&Hh, g_Hh);
    cudaGetSymbolAddress((void**)&Wqkvh, g_Wqkvh);
    cudaGetSymbolAddress((void**)&Woh, g_Woh);
    cudaGetSymbolAddress((void**)&Qh, g_Qh);
    cudaGetSymbolAddress((void**)&KVh, g_KVh);
    cudaGetSymbolAddress((void**)&Oh, g_Oh);

    cudaFuncSetAttribute(gemm_fp16, cudaFuncAttributeMaxDynamicSharedMemorySize, XSMEM);
    cudaFuncSetAttribute(flash_attn_fp16, cudaFuncAttributeMaxDynamicSharedMemorySize, FA_SMEM);

    const int TB = 256;
    // fp16 conversions (weights packed: Wq | Wk | Wv)
    cvt_fp16<<<(S_LEN * HIDDIM / 4 + TB - 1) / TB, TB>>>(H, Hh, S_LEN * HIDDIM / 4);
    cvt_fp16<<<(HIDDIM * HIDDIM / 4 + TB - 1) / TB, TB>>>(Wq, Wqkvh, HIDDIM * HIDDIM / 4);
    cvt_fp16<<<(NKV * HD * HIDDIM / 4 + TB - 1) / TB, TB>>>(
        Wk, Wqkvh + (size_t)HIDDIM * HIDDIM, NKV * HD * HIDDIM / 4);
    cvt_fp16<<<(NKV * HD * HIDDIM / 4 + TB - 1) / TB, TB>>>(
        Wv, Wqkvh + (size_t)(HIDDIM + NKV * HD) * HIDDIM, NKV * HD * HIDDIM / 4);
    cvt_fp16<<<(HIDDIM * HIDDIM / 4 + TB - 1) / TB, TB>>>(Wo, Woh, HIDDIM * HIDDIM / 4);

    // fused QKV projection
    gemm_fp16<<<dim3(QKVN / 128, S_LEN / 256), 512, XSMEM>>>(Hh, Wqkvh, qkv,
                                                             S_LEN, QKVN, HIDDIM);
    // RoPE + fp16 conversion (scale folded into Q)
    rope_cvt<<<(S_LEN * 48 * 64 + TB - 1) / TB, TB>>>(qkv, Qh, KVh);

    // fp16 flash attention -> fp16 O
    flash_attn_fp16<<<dim3(S_LEN / 64, NH), 128, FA_SMEM>>>(Qh, KVh, Oh);

    // output projection -> fp32 d_out
    gemm_fp16<<<dim3(HIDDIM / 128, S_LEN / 256), 512, XSMEM>>>(Oh, Woh, out,
                                                               S_LEN, HIDDIM, HIDDIM);
}